// round 2
// baseline (speedup 1.0000x reference)
#include <cuda_runtime.h>
#include <math.h>

#define BSZ 4
#define NNODE 2048
#define NINP 128
#define NFEAT 64
#define NHEADS 4
#define BH (BSZ*NHEADS)

// ---- scratch (static device globals; no allocation) ----
__device__ float    d_g[(size_t)BH*NNODE*NFEAT];    // e_j * h_j      (8 MB)
__device__ float    d_num[(size_t)BH*NNODE*NFEAT];  // Adj @ g        (8 MB)
__device__ float    d_e[BH*NNODE];                  // exp(s_dst)
__device__ float    d_rinv[BH*NNODE];               // 1 / (Adj @ e)
__device__ unsigned d_bits[NNODE*(NNODE/32)];       // packed adjacency (512 KB)

// ---------------------------------------------------------------------------
// k0: pack adjacency int32 -> bitmask. bit k of word w of row r  <->  adj[r][w*32+k]
// ---------------------------------------------------------------------------
__global__ void k0_pack(const int* __restrict__ adj) {
    unsigned idx = blockIdx.x * 256u + threadIdx.x;   // one thread per adj element
    unsigned row = idx >> 11;
    unsigned j   = idx & 2047u;
    unsigned v   = (adj[(size_t)row * NNODE + j] != 0) ? 1u : 0u;
    unsigned w   = __ballot_sync(0xffffffffu, v);
    if ((threadIdx.x & 31u) == 0u)
        d_bits[row * 64u + (j >> 5)] = w;
}

// ---------------------------------------------------------------------------
// k1: h = inp @ W[head] + b[head];  e = exp(h . a_dst);  g = e * h
// CTA: (node-tile of 64, head, batch). 256 threads: thread = (node, 16-feat quarter)
// ---------------------------------------------------------------------------
__global__ void k1_proj(const float* __restrict__ inp, const float* __restrict__ W,
                        const float* __restrict__ bias, const float* __restrict__ a_dst) {
    __shared__ float s_inp[64 * 64];
    __shared__ float s_W[64 * 64];

    int head = blockIdx.y, bb = blockIdx.z;
    int n0 = blockIdx.x * 64;
    int t = threadIdx.x;
    int node = t >> 2;
    int f0 = (t & 3) * 16;

    float4 acc[4];
#pragma unroll
    for (int i = 0; i < 4; i++)
        acc[i] = *(const float4*)(bias + head * NFEAT + f0 + i * 4);

    for (int kc = 0; kc < 2; kc++) {
        __syncthreads();
#pragma unroll
        for (int i = 0; i < 4; i++) {
            int li = t + i * 256;          // 0..1023 float4 slots
            int rr = li >> 4, c4 = li & 15;
            ((float4*)s_inp)[li] = *(const float4*)(inp + ((size_t)bb * NNODE + n0 + rr) * NINP + kc * 64 + c4 * 4);
            ((float4*)s_W)[li]   = *(const float4*)(W + (size_t)head * NINP * NFEAT + (size_t)(kc * 64 + rr) * NFEAT + c4 * 4);
        }
        __syncthreads();
#pragma unroll 8
        for (int k = 0; k < 64; k++) {
            float a = s_inp[node * 64 + k];
            const float4* wr = (const float4*)(s_W + k * 64 + f0);
            float4 w0 = wr[0], w1 = wr[1], w2 = wr[2], w3 = wr[3];
            acc[0].x = fmaf(a, w0.x, acc[0].x); acc[0].y = fmaf(a, w0.y, acc[0].y);
            acc[0].z = fmaf(a, w0.z, acc[0].z); acc[0].w = fmaf(a, w0.w, acc[0].w);
            acc[1].x = fmaf(a, w1.x, acc[1].x); acc[1].y = fmaf(a, w1.y, acc[1].y);
            acc[1].z = fmaf(a, w1.z, acc[1].z); acc[1].w = fmaf(a, w1.w, acc[1].w);
            acc[2].x = fmaf(a, w2.x, acc[2].x); acc[2].y = fmaf(a, w2.y, acc[2].y);
            acc[2].z = fmaf(a, w2.z, acc[2].z); acc[2].w = fmaf(a, w2.w, acc[2].w);
            acc[3].x = fmaf(a, w3.x, acc[3].x); acc[3].y = fmaf(a, w3.y, acc[3].y);
            acc[3].z = fmaf(a, w3.z, acc[3].z); acc[3].w = fmaf(a, w3.w, acc[3].w);
        }
    }

    // s_dst = h . a_dst  (partial over 16 feats, reduce across the 4 fq threads)
    const float4* ad = (const float4*)(a_dst + head * NFEAT + f0);
    float4 a0 = ad[0], a1 = ad[1], a2 = ad[2], a3 = ad[3];
    float s = acc[0].x * a0.x + acc[0].y * a0.y + acc[0].z * a0.z + acc[0].w * a0.w
            + acc[1].x * a1.x + acc[1].y * a1.y + acc[1].z * a1.z + acc[1].w * a1.w
            + acc[2].x * a2.x + acc[2].y * a2.y + acc[2].z * a2.z + acc[2].w * a2.w
            + acc[3].x * a3.x + acc[3].y * a3.y + acc[3].z * a3.z + acc[3].w * a3.w;
    s += __shfl_xor_sync(0xffffffffu, s, 1);
    s += __shfl_xor_sync(0xffffffffu, s, 2);
    float e = expf(s);

    int bh = bb * NHEADS + head;
    size_t base = (((size_t)bh) * NNODE + n0 + node) * NFEAT + f0;
    float4* gd = (float4*)(d_g + base);
    gd[0] = make_float4(acc[0].x * e, acc[0].y * e, acc[0].z * e, acc[0].w * e);
    gd[1] = make_float4(acc[1].x * e, acc[1].y * e, acc[1].z * e, acc[1].w * e);
    gd[2] = make_float4(acc[2].x * e, acc[2].y * e, acc[2].z * e, acc[2].w * e);
    gd[3] = make_float4(acc[3].x * e, acc[3].y * e, acc[3].z * e, acc[3].w * e);
    if ((t & 3) == 0)
        d_e[bh * NNODE + n0 + node] = e;
}

// ---------------------------------------------------------------------------
// k2: num = Adj @ g ;  rowsum = Adj @ e  (per bh). fp32 FFMA, bit->float trick.
// CTA: (row-tile of 64, bh). 256 threads: thread = (row, 16-feat quarter).
// ---------------------------------------------------------------------------
__global__ void k2_agg() {
    __shared__ float s_g[128 * NFEAT];
    __shared__ float s_e[128];

    int bh = blockIdx.y;
    int row = blockIdx.x * 64 + (threadIdx.x >> 2);
    int f0 = (threadIdx.x & 3) * 16;
    const float* gsrc = d_g + (size_t)bh * NNODE * NFEAT;
    const float* esrc = d_e + bh * NNODE;

    float4 acc[4];
#pragma unroll
    for (int i = 0; i < 4; i++) acc[i] = make_float4(0.f, 0.f, 0.f, 0.f);
    float rsum = 0.f;

    for (int jt = 0; jt < NNODE / 128; jt++) {
        __syncthreads();
        const float4* gs = (const float4*)(gsrc + (size_t)jt * 128 * NFEAT);
        float4* gd = (float4*)s_g;
#pragma unroll
        for (int i = 0; i < 8; i++)
            gd[threadIdx.x + i * 256] = gs[threadIdx.x + i * 256];
        if (threadIdx.x < 128)
            s_e[threadIdx.x] = esrc[jt * 128 + threadIdx.x];
        __syncthreads();

        const unsigned* bw = d_bits + row * 64 + jt * 4;
#pragma unroll
        for (int w = 0; w < 4; w++) {
            unsigned m = bw[w];
            int jb = w * 32;
#pragma unroll
            for (int k = 0; k < 32; k++) {
                float af = __uint_as_float((m & 1u) * 0x3f800000u);
                m >>= 1;
                const float4* gr = (const float4*)(s_g + (jb + k) * NFEAT + f0);
                float4 g0 = gr[0], g1 = gr[1], g2 = gr[2], g3 = gr[3];
                acc[0].x = fmaf(af, g0.x, acc[0].x); acc[0].y = fmaf(af, g0.y, acc[0].y);
                acc[0].z = fmaf(af, g0.z, acc[0].z); acc[0].w = fmaf(af, g0.w, acc[0].w);
                acc[1].x = fmaf(af, g1.x, acc[1].x); acc[1].y = fmaf(af, g1.y, acc[1].y);
                acc[1].z = fmaf(af, g1.z, acc[1].z); acc[1].w = fmaf(af, g1.w, acc[1].w);
                acc[2].x = fmaf(af, g2.x, acc[2].x); acc[2].y = fmaf(af, g2.y, acc[2].y);
                acc[2].z = fmaf(af, g2.z, acc[2].z); acc[2].w = fmaf(af, g2.w, acc[2].w);
                acc[3].x = fmaf(af, g3.x, acc[3].x); acc[3].y = fmaf(af, g3.y, acc[3].y);
                acc[3].z = fmaf(af, g3.z, acc[3].z); acc[3].w = fmaf(af, g3.w, acc[3].w);
                rsum = fmaf(af, s_e[jb + k], rsum);
            }
        }
    }

    float* nd = d_num + ((size_t)bh * NNODE + row) * NFEAT + f0;
#pragma unroll
    for (int i = 0; i < 4; i++) ((float4*)nd)[i] = acc[i];
    if ((threadIdx.x & 3) == 0)
        d_rinv[bh * NNODE + row] = 1.f / rsum;
}

// ---------------------------------------------------------------------------
// k3: att[bh][i][j] = bit ? e_j * rinv_i : 0.  Coalesced float4 stores.
// CTA: (8-row tile, bh). warp per row; lane covers 4 consecutive j.
// ---------------------------------------------------------------------------
__global__ void k3_att(float* __restrict__ att) {
    __shared__ float s_e[NNODE];
    int bh = blockIdx.y;
    for (int i = threadIdx.x; i < NNODE; i += 256)
        s_e[i] = d_e[bh * NNODE + i];
    __syncthreads();

    int warp = threadIdx.x >> 5, lane = threadIdx.x & 31;
    int row = blockIdx.x * 8 + warp;
    float rinv = d_rinv[bh * NNODE + row];
    const unsigned* bw = d_bits + row * 64;
    float* dst = att + ((size_t)bh * NNODE + row) * NNODE;

#pragma unroll
    for (int c = 0; c < 16; c++) {
        int j = c * 128 + lane * 4;
        unsigned m = bw[j >> 5] >> (j & 31);
        float4 v;
        v.x = (m & 1u) ? s_e[j]     * rinv : 0.f;
        v.y = (m & 2u) ? s_e[j + 1] * rinv : 0.f;
        v.z = (m & 4u) ? s_e[j + 2] * rinv : 0.f;
        v.w = (m & 8u) ? s_e[j + 3] * rinv : 0.f;
        *(float4*)(dst + j) = v;
    }
}

// ---------------------------------------------------------------------------
// k4: out[b][n][head*64+f] = elu(num * rinv)
// ---------------------------------------------------------------------------
__global__ void k4_out(float* __restrict__ out) {
    unsigned idx = blockIdx.x * 256u + threadIdx.x;  // float4 index
    unsigned ch4 = idx & 63u;
    unsigned bn  = idx >> 6;
    unsigned n   = bn & 2047u;
    unsigned b   = bn >> 11;
    unsigned f4  = ch4 * 4u;
    unsigned head = f4 >> 6;
    unsigned f    = f4 & 63u;
    unsigned bh   = b * NHEADS + head;
    float rinv = d_rinv[bh * NNODE + n];
    float4 v = *(const float4*)(d_num + ((size_t)bh * NNODE + n) * NFEAT + f);
    float x;
    x = v.x * rinv; v.x = x > 0.f ? x : expm1f(x);
    x = v.y * rinv; v.y = x > 0.f ? x : expm1f(x);
    x = v.z * rinv; v.z = x > 0.f ? x : expm1f(x);
    x = v.w * rinv; v.w = x > 0.f ? x : expm1f(x);
    *(float4*)(out + ((size_t)b * NNODE + n) * (NHEADS * NFEAT) + f4) = v;
}

// ---------------------------------------------------------------------------
extern "C" void kernel_launch(void* const* d_in, const int* in_sizes, int n_in,
                              void* d_out, int out_size) {
    const float* inp   = (const float*)d_in[0];
    const int*   adj   = (const int*)  d_in[1];
    const float* W     = (const float*)d_in[2];
    const float* bias  = (const float*)d_in[3];
    const float* a_dst = (const float*)d_in[5];
    (void)in_sizes; (void)n_in;

    float* out = (float*)d_out;
    const size_t OUT_E = (size_t)BSZ * NNODE * NHEADS * NFEAT;        // 2,097,152
    const size_t ATT_E = (size_t)BSZ * NHEADS * NNODE * NNODE;        // 67,108,864
    float* out_main = nullptr;
    float* out_att  = nullptr;
    if ((size_t)out_size >= OUT_E + ATT_E) { out_main = out; out_att = out + OUT_E; }
    else if ((size_t)out_size == ATT_E)    { out_att = out; }
    else                                   { out_main = out; }

    k0_pack<<<(NNODE * NNODE) / 256, 256>>>(adj);
    k1_proj<<<dim3(NNODE / 64, NHEADS, BSZ), 256>>>(inp, W, bias, a_dst);
    k2_agg<<<dim3(NNODE / 64, BH), 256>>>();
    if (out_att)  k3_att<<<dim3(NNODE / 8, BH), 256>>>(out_att);
    if (out_main) k4_out<<<(BSZ * NNODE * NHEADS * NFEAT / 4) / 256, 256>>>(out_main);
}

// round 4
// speedup vs baseline: 5.5590x; 5.5590x over previous
#include <cuda_runtime.h>
#include <cuda_bf16.h>
#include <math.h>
#include <stdint.h>

#define BSZ 4
#define NNODE 2048
#define NINP 128
#define NFEAT 64
#define NHEADS 4
#define BH (BSZ*NHEADS)

// ---- scratch (static device globals; no allocation) ----
__device__ __nv_bfloat16 d_adjh[(size_t)NNODE*NNODE];       // Adj as bf16 (8 MB)
__device__ unsigned      d_bits[NNODE*(NNODE/32)];          // packed adjacency
__device__ __nv_bfloat16 d_gh[(size_t)BH*NNODE*NFEAT];      // hi(e*h)  [bh][j][f]
__device__ __nv_bfloat16 d_gl[(size_t)BH*NNODE*NFEAT];      // lo residual
__device__ float         d_e[BH*NNODE];                     // exp(s_dst)
__device__ float         d_rinv[BH*NNODE];                  // 1/(Adj@e)

__device__ __forceinline__ uint32_t smem_u32(const void* p) {
    return (uint32_t)__cvta_generic_to_shared(p);
}
__device__ __forceinline__ void ldsm_x4(uint32_t* r, uint32_t addr) {
    asm volatile("ldmatrix.sync.aligned.m8n8.x4.shared.b16 {%0,%1,%2,%3}, [%4];"
                 : "=r"(r[0]), "=r"(r[1]), "=r"(r[2]), "=r"(r[3]) : "r"(addr));
}
__device__ __forceinline__ void ldsm_x4_t(uint32_t* r, uint32_t addr) {
    asm volatile("ldmatrix.sync.aligned.m8n8.x4.trans.shared.b16 {%0,%1,%2,%3}, [%4];"
                 : "=r"(r[0]), "=r"(r[1]), "=r"(r[2]), "=r"(r[3]) : "r"(addr));
}
__device__ __forceinline__ void mma_bf16(float* c, const uint32_t* a, const uint32_t* b) {
    asm volatile(
        "mma.sync.aligned.m16n8k16.row.col.f32.bf16.bf16.f32 "
        "{%0,%1,%2,%3}, {%4,%5,%6,%7}, {%8,%9}, {%0,%1,%2,%3};"
        : "+f"(c[0]), "+f"(c[1]), "+f"(c[2]), "+f"(c[3])
        : "r"(a[0]), "r"(a[1]), "r"(a[2]), "r"(a[3]), "r"(b[0]), "r"(b[1]));
}

// ---------------------------------------------------------------------------
// k0: adj int32 -> bf16 matrix + bitmask
// ---------------------------------------------------------------------------
__global__ void k0_pack(const int* __restrict__ adj) {
    unsigned idx = blockIdx.x * 256u + threadIdx.x;
    unsigned row = idx >> 11;
    unsigned j   = idx & 2047u;
    unsigned v   = (adj[(size_t)row * NNODE + j] != 0) ? 1u : 0u;
    d_adjh[(size_t)row * NNODE + j] = __float2bfloat16(v ? 1.f : 0.f);
    unsigned w = __ballot_sync(0xffffffffu, v);
    if ((threadIdx.x & 31u) == 0u)
        d_bits[row * 64u + (j >> 5)] = w;
}

// ---------------------------------------------------------------------------
// k1: h = inp @ W[head] + b;  e = exp(h . a_dst);  g = e*h -> bf16 hi/lo,
//     stored [bh][j][f] (k-major for the MMA B operand)
// ---------------------------------------------------------------------------
__global__ void k1_proj(const float* __restrict__ inp, const float* __restrict__ W,
                        const float* __restrict__ bias, const float* __restrict__ a_dst) {
    __shared__ float s_inp[64 * 64];
    __shared__ float s_W[64 * 64];

    int head = blockIdx.y, bb = blockIdx.z;
    int n0 = blockIdx.x * 64;
    int t = threadIdx.x;
    int node = t >> 2;
    int f0 = (t & 3) * 16;

    float4 acc[4];
#pragma unroll
    for (int i = 0; i < 4; i++)
        acc[i] = *(const float4*)(bias + head * NFEAT + f0 + i * 4);

    for (int kc = 0; kc < 2; kc++) {
        __syncthreads();
#pragma unroll
        for (int i = 0; i < 4; i++) {
            int li = t + i * 256;
            int rr = li >> 4, c4 = li & 15;
            ((float4*)s_inp)[li] = *(const float4*)(inp + ((size_t)bb * NNODE + n0 + rr) * NINP + kc * 64 + c4 * 4);
            ((float4*)s_W)[li]   = *(const float4*)(W + (size_t)head * NINP * NFEAT + (size_t)(kc * 64 + rr) * NFEAT + c4 * 4);
        }
        __syncthreads();
#pragma unroll 8
        for (int k = 0; k < 64; k++) {
            float a = s_inp[node * 64 + k];
            const float4* wr = (const float4*)(s_W + k * 64 + f0);
            float4 w0 = wr[0], w1 = wr[1], w2 = wr[2], w3 = wr[3];
            acc[0].x = fmaf(a, w0.x, acc[0].x); acc[0].y = fmaf(a, w0.y, acc[0].y);
            acc[0].z = fmaf(a, w0.z, acc[0].z); acc[0].w = fmaf(a, w0.w, acc[0].w);
            acc[1].x = fmaf(a, w1.x, acc[1].x); acc[1].y = fmaf(a, w1.y, acc[1].y);
            acc[1].z = fmaf(a, w1.z, acc[1].z); acc[1].w = fmaf(a, w1.w, acc[1].w);
            acc[2].x = fmaf(a, w2.x, acc[2].x); acc[2].y = fmaf(a, w2.y, acc[2].y);
            acc[2].z = fmaf(a, w2.z, acc[2].z); acc[2].w = fmaf(a, w2.w, acc[2].w);
            acc[3].x = fmaf(a, w3.x, acc[3].x); acc[3].y = fmaf(a, w3.y, acc[3].y);
            acc[3].z = fmaf(a, w3.z, acc[3].z); acc[3].w = fmaf(a, w3.w, acc[3].w);
        }
    }

    const float4* ad = (const float4*)(a_dst + head * NFEAT + f0);
    float4 a0 = ad[0], a1 = ad[1], a2 = ad[2], a3 = ad[3];
    float s = acc[0].x * a0.x + acc[0].y * a0.y + acc[0].z * a0.z + acc[0].w * a0.w
            + acc[1].x * a1.x + acc[1].y * a1.y + acc[1].z * a1.z + acc[1].w * a1.w
            + acc[2].x * a2.x + acc[2].y * a2.y + acc[2].z * a2.z + acc[2].w * a2.w
            + acc[3].x * a3.x + acc[3].y * a3.y + acc[3].z * a3.z + acc[3].w * a3.w;
    s += __shfl_xor_sync(0xffffffffu, s, 1);
    s += __shfl_xor_sync(0xffffffffu, s, 2);
    float e = expf(s);

    float vals[16];
#pragma unroll
    for (int i = 0; i < 4; i++) ((float4*)vals)[i] = acc[i];

    int bh = bb * NHEADS + head;
    size_t base = ((size_t)bh * NNODE + (n0 + node)) * NFEAT + f0;
    __nv_bfloat16 hi16[16], lo16[16];
#pragma unroll
    for (int i = 0; i < 16; i++) {
        float g = vals[i] * e;
        __nv_bfloat16 hi = __float2bfloat16(g);
        hi16[i] = hi;
        lo16[i] = __float2bfloat16(g - __bfloat162float(hi));
    }
#pragma unroll
    for (int i = 0; i < 2; i++) {
        ((uint4*)(d_gh + base))[i] = ((const uint4*)hi16)[i];
        ((uint4*)(d_gl + base))[i] = ((const uint4*)lo16)[i];
    }
    if ((t & 3) == 0)
        d_e[bh * NNODE + n0 + node] = e;
}

// ---------------------------------------------------------------------------
// k2: num = Adj @ (g_hi + g_lo) via mma.sync bf16, fp32 accum.
//     Fused epilogue: out = elu(num * rinv) directly.
// CTA: 256 thr = 8 warps (4 m-warps x 2 n-warps). Tile M=128, N=64, one bh.
// ---------------------------------------------------------------------------
#define APAD 72   // bf16 elems per smem row (144 B -> conflict-free ldmatrix)

__global__ void __launch_bounds__(256) k2_mma(float* __restrict__ out_main) {
    __shared__ __nv_bfloat16 sA[128 * APAD];
    __shared__ __nv_bfloat16 sB[2][64 * APAD];

    const int tid = threadIdx.x;
    const int warp = tid >> 5, lane = tid & 31;
    const int wm = warp & 3, wn = warp >> 2;          // 4 x 2 warp grid
    const int m0 = blockIdx.x * 128;
    const int bh = blockIdx.y;

    const __nv_bfloat16* srcA = d_adjh + (size_t)m0 * NNODE;
    const __nv_bfloat16* srcH = d_gh + (size_t)bh * NNODE * NFEAT;
    const __nv_bfloat16* srcL = d_gl + (size_t)bh * NNODE * NFEAT;

    float acc[2][4][4];
#pragma unroll
    for (int mt = 0; mt < 2; mt++)
#pragma unroll
        for (int nt = 0; nt < 4; nt++)
#pragma unroll
            for (int i = 0; i < 4; i++) acc[mt][nt][i] = 0.f;

    for (int c = 0; c < 32; c++) {
        const int cb = c * 64;
        __syncthreads();
        // A tile: 128 rows x 64 bf16 (1024 x 16B chunks)
#pragma unroll
        for (int i = 0; i < 4; i++) {
            int ch = tid + i * 256;
            int rr = ch >> 3, cc = ch & 7;
            uint4 v = *(const uint4*)(srcA + (size_t)rr * NNODE + cb + cc * 8);
            *(uint4*)(sA + rr * APAD + cc * 8) = v;
        }
        // B tiles: hi/lo panels, each 64 k-rows x 64 feats (512 chunks each)
#pragma unroll
        for (int i = 0; i < 4; i++) {
            int ch = tid + i * 256;
            int p = ch >> 9, r = (ch >> 3) & 63, cc = ch & 7;
            const __nv_bfloat16* src = p ? srcL : srcH;
            uint4 v = *(const uint4*)(src + (size_t)(cb + r) * NFEAT + cc * 8);
            *(uint4*)(sB[p] + r * APAD + cc * 8) = v;
        }
        __syncthreads();

#pragma unroll
        for (int ks = 0; ks < 4; ks++) {
            uint32_t af[2][4];
#pragma unroll
            for (int mt = 0; mt < 2; mt++) {
                uint32_t addr = smem_u32(sA + (wm * 32 + mt * 16 + (lane & 15)) * APAD
                                            + ks * 16 + (lane >> 4) * 8);
                ldsm_x4(af[mt], addr);
            }
#pragma unroll
            for (int p = 0; p < 2; p++) {
                uint32_t bf[2][4];
#pragma unroll
                for (int np = 0; np < 2; np++) {
                    uint32_t addr = smem_u32(sB[p] + (ks * 16 + (lane & 15)) * APAD
                                                 + wn * 32 + np * 16 + (lane >> 4) * 8);
                    ldsm_x4_t(bf[np], addr);
                }
#pragma unroll
                for (int mt = 0; mt < 2; mt++) {
#pragma unroll
                    for (int nt = 0; nt < 4; nt++)
                        mma_bf16(acc[mt][nt], af[mt], bf[nt >> 1] + (nt & 1) * 2);
                }
            }
        }
    }

    // fused epilogue: out[b][node][head*64 + f] = elu(acc * rinv)
    if (out_main) {
        const int b = bh >> 2, head = bh & 3;
#pragma unroll
        for (int mt = 0; mt < 2; mt++) {
            int r0 = m0 + wm * 32 + mt * 16 + (lane >> 2);
            float ri0 = d_rinv[bh * NNODE + r0];
            float ri1 = d_rinv[bh * NNODE + r0 + 8];
            float* o0 = out_main + ((size_t)b * NNODE + r0) * (NHEADS * NFEAT) + head * NFEAT;
            float* o1 = o0 + 8 * (NHEADS * NFEAT);
#pragma unroll
            for (int nt = 0; nt < 4; nt++) {
                int col = wn * 32 + nt * 8 + (lane & 3) * 2;
                float x0 = acc[mt][nt][0] * ri0, x1 = acc[mt][nt][1] * ri0;
                float x2 = acc[mt][nt][2] * ri1, x3 = acc[mt][nt][3] * ri1;
                x0 = x0 > 0.f ? x0 : expm1f(x0);
                x1 = x1 > 0.f ? x1 : expm1f(x1);
                x2 = x2 > 0.f ? x2 : expm1f(x2);
                x3 = x3 > 0.f ? x3 : expm1f(x3);
                *(float2*)(o0 + col) = make_float2(x0, x1);
                *(float2*)(o1 + col) = make_float2(x2, x3);
            }
        }
    }
}

// ---------------------------------------------------------------------------
// k2b: rowsum = Adj @ e via bitmask;  rinv = 1/rowsum
// ---------------------------------------------------------------------------
__global__ void k2b_rowsum() {
    __shared__ float s_e[NNODE];
    int bh = blockIdx.y;
    for (int i = threadIdx.x; i < NNODE; i += 256)
        s_e[i] = d_e[bh * NNODE + i];
    __syncthreads();
    int warp = threadIdx.x >> 5, lane = threadIdx.x & 31;
#pragma unroll 1
    for (int rr = 0; rr < 8; rr++) {
        int rowi = blockIdx.x * 64 + warp * 8 + rr;
        const unsigned* bw = d_bits + rowi * 64;
        float s = 0.f;
#pragma unroll 8
        for (int k = 0; k < 64; k++) {
            unsigned m = bw[k];
            s = fmaf(__uint_as_float(((m >> lane) & 1u) * 0x3f800000u), s_e[k * 32 + lane], s);
        }
        s += __shfl_xor_sync(0xffffffffu, s, 16);
        s += __shfl_xor_sync(0xffffffffu, s, 8);
        s += __shfl_xor_sync(0xffffffffu, s, 4);
        s += __shfl_xor_sync(0xffffffffu, s, 2);
        s += __shfl_xor_sync(0xffffffffu, s, 1);
        if (lane == 0)
            d_rinv[bh * NNODE + rowi] = 1.f / s;
    }
}

// ---------------------------------------------------------------------------
// k3: att[bh][i][j] = bit ? e_j * rinv_i : 0  (streaming float4 stores)
// ---------------------------------------------------------------------------
__global__ void k3_att(float* __restrict__ att) {
    __shared__ float s_e[NNODE];
    int bh = blockIdx.y;
    for (int i = threadIdx.x; i < NNODE; i += 256)
        s_e[i] = d_e[bh * NNODE + i];
    __syncthreads();

    int warp = threadIdx.x >> 5, lane = threadIdx.x & 31;
    int row = blockIdx.x * 8 + warp;
    float rinv = d_rinv[bh * NNODE + row];
    const unsigned* bw = d_bits + row * 64;
    float* dst = att + ((size_t)bh * NNODE + row) * NNODE;

#pragma unroll
    for (int c = 0; c < 16; c++) {
        int j = c * 128 + lane * 4;
        unsigned m = bw[j >> 5] >> (j & 31);
        float4 v;
        v.x = (m & 1u) ? s_e[j]     * rinv : 0.f;
        v.y = (m & 2u) ? s_e[j + 1] * rinv : 0.f;
        v.z = (m & 4u) ? s_e[j + 2] * rinv : 0.f;
        v.w = (m & 8u) ? s_e[j + 3] * rinv : 0.f;
        __stcs((float4*)(dst + j), v);
    }
}

// ---------------------------------------------------------------------------
extern "C" void kernel_launch(void* const* d_in, const int* in_sizes, int n_in,
                              void* d_out, int out_size) {
    const float* inp   = (const float*)d_in[0];
    const int*   adj   = (const int*)  d_in[1];
    const float* W     = (const float*)d_in[2];
    const float* bias  = (const float*)d_in[3];
    const float* a_dst = (const float*)d_in[5];
    (void)in_sizes; (void)n_in;

    float* out = (float*)d_out;
    const size_t OUT_E = (size_t)BSZ * NNODE * NHEADS * NFEAT;
    const size_t ATT_E = (size_t)BSZ * NHEADS * NNODE * NNODE;
    float* out_main = nullptr;
    float* out_att  = nullptr;
    if ((size_t)out_size >= OUT_E + ATT_E) { out_main = out; out_att = out + OUT_E; }
    else if ((size_t)out_size == ATT_E)    { out_att = out; }
    else                                   { out_main = out; }

    k0_pack<<<(NNODE * NNODE) / 256, 256>>>(adj);
    k1_proj<<<dim3(NNODE / 64, NHEADS, BSZ), 256>>>(inp, W, bias, a_dst);
    k2b_rowsum<<<dim3(NNODE / 64, BH), 256>>>();
    k2_mma<<<dim3(NNODE / 128, BH), 256>>>(out_main);
    if (out_att) k3_att<<<dim3(NNODE / 8, BH), 256>>>(out_att);
}

// round 5
// speedup vs baseline: 6.2365x; 1.1219x over previous
#include <cuda_runtime.h>
#include <cuda_bf16.h>
#include <math.h>
#include <stdint.h>

#define BSZ 4
#define NNODE 2048
#define NINP 128
#define NFEAT 64
#define NHEADS 4
#define BH (BSZ*NHEADS)

// ---- scratch (static device globals; no allocation) ----
__device__ __nv_bfloat16 d_adjh[(size_t)NNODE*NNODE];       // Adj as bf16 (8 MB)
__device__ unsigned      d_bits[NNODE*(NNODE/32)];          // packed adjacency
__device__ __nv_bfloat16 d_gh[(size_t)BH*NNODE*NFEAT];      // hi(e*h)  [bh][j][f]
__device__ __nv_bfloat16 d_gl[(size_t)BH*NNODE*NFEAT];      // lo residual
__device__ __nv_bfloat16 d_eh[BH*NNODE];                    // hi(e)
__device__ __nv_bfloat16 d_el[BH*NNODE];                    // lo(e)
__device__ float         d_e[BH*NNODE];                     // exp(s_dst) fp32
__device__ float         d_rinv[BH*NNODE];                  // 1/(Adj@e)

__device__ __forceinline__ uint32_t smem_u32(const void* p) {
    return (uint32_t)__cvta_generic_to_shared(p);
}
__device__ __forceinline__ void ldsm_x4(uint32_t* r, uint32_t addr) {
    asm volatile("ldmatrix.sync.aligned.m8n8.x4.shared.b16 {%0,%1,%2,%3}, [%4];"
                 : "=r"(r[0]), "=r"(r[1]), "=r"(r[2]), "=r"(r[3]) : "r"(addr));
}
__device__ __forceinline__ void ldsm_x4_t(uint32_t* r, uint32_t addr) {
    asm volatile("ldmatrix.sync.aligned.m8n8.x4.trans.shared.b16 {%0,%1,%2,%3}, [%4];"
                 : "=r"(r[0]), "=r"(r[1]), "=r"(r[2]), "=r"(r[3]) : "r"(addr));
}
__device__ __forceinline__ void ldsm_x2_t(uint32_t* r, uint32_t addr) {
    asm volatile("ldmatrix.sync.aligned.m8n8.x2.trans.shared.b16 {%0,%1}, [%2];"
                 : "=r"(r[0]), "=r"(r[1]) : "r"(addr));
}
__device__ __forceinline__ void mma_bf16(float* c, const uint32_t* a, const uint32_t* b) {
    asm volatile(
        "mma.sync.aligned.m16n8k16.row.col.f32.bf16.bf16.f32 "
        "{%0,%1,%2,%3}, {%4,%5,%6,%7}, {%8,%9}, {%0,%1,%2,%3};"
        : "+f"(c[0]), "+f"(c[1]), "+f"(c[2]), "+f"(c[3])
        : "r"(a[0]), "r"(a[1]), "r"(a[2]), "r"(a[3]), "r"(b[0]), "r"(b[1]));
}
#define CP_ASYNC16(dst, src) \
    asm volatile("cp.async.cg.shared.global [%0], [%1], 16;" :: "r"(dst), "l"(src))
#define CP_COMMIT() asm volatile("cp.async.commit_group;")
#define CP_WAIT1()  asm volatile("cp.async.wait_group 1;")

// ---------------------------------------------------------------------------
// kA: fused k0 (adj pack) + k1 (projection). Branch on blockIdx.x.
//   blocks [0,512): k1;  blocks [512, 512+16384): k0
// ---------------------------------------------------------------------------
#define K1_BLOCKS 512

__global__ void __launch_bounds__(256) kA_prep(
        const float* __restrict__ inp, const int* __restrict__ adj,
        const float* __restrict__ W, const float* __restrict__ bias,
        const float* __restrict__ a_dst) {
    __shared__ float s_inp[64 * 64];
    __shared__ float s_W[64 * 64];
    const int bid = blockIdx.x;
    const int t = threadIdx.x;

    if (bid >= K1_BLOCKS) {
        // ---- k0: adj int32 -> bf16 + bitmask ----
        unsigned idx = (bid - K1_BLOCKS) * 256u + t;
        unsigned row = idx >> 11;
        unsigned j   = idx & 2047u;
        unsigned v   = (adj[(size_t)row * NNODE + j] != 0) ? 1u : 0u;
        d_adjh[(size_t)row * NNODE + j] = __float2bfloat16(v ? 1.f : 0.f);
        unsigned w = __ballot_sync(0xffffffffu, v);
        if ((t & 31u) == 0u)
            d_bits[row * 64u + (j >> 5)] = w;
        return;
    }

    // ---- k1: h = inp @ W + b; e = exp(h . a_dst); g hi/lo [bh][j][f] ----
    int n0   = (bid & 31) * 64;
    int head = (bid >> 5) & 3;
    int bb   = bid >> 7;
    int node = t >> 2;
    int f0 = (t & 3) * 16;

    float4 acc[4];
#pragma unroll
    for (int i = 0; i < 4; i++)
        acc[i] = *(const float4*)(bias + head * NFEAT + f0 + i * 4);

    for (int kc = 0; kc < 2; kc++) {
        __syncthreads();
#pragma unroll
        for (int i = 0; i < 4; i++) {
            int li = t + i * 256;
            int rr = li >> 4, c4 = li & 15;
            ((float4*)s_inp)[li] = *(const float4*)(inp + ((size_t)bb * NNODE + n0 + rr) * NINP + kc * 64 + c4 * 4);
            ((float4*)s_W)[li]   = *(const float4*)(W + (size_t)head * NINP * NFEAT + (size_t)(kc * 64 + rr) * NFEAT + c4 * 4);
        }
        __syncthreads();
#pragma unroll 8
        for (int k = 0; k < 64; k++) {
            float a = s_inp[node * 64 + k];
            const float4* wr = (const float4*)(s_W + k * 64 + f0);
            float4 w0 = wr[0], w1 = wr[1], w2 = wr[2], w3 = wr[3];
            acc[0].x = fmaf(a, w0.x, acc[0].x); acc[0].y = fmaf(a, w0.y, acc[0].y);
            acc[0].z = fmaf(a, w0.z, acc[0].z); acc[0].w = fmaf(a, w0.w, acc[0].w);
            acc[1].x = fmaf(a, w1.x, acc[1].x); acc[1].y = fmaf(a, w1.y, acc[1].y);
            acc[1].z = fmaf(a, w1.z, acc[1].z); acc[1].w = fmaf(a, w1.w, acc[1].w);
            acc[2].x = fmaf(a, w2.x, acc[2].x); acc[2].y = fmaf(a, w2.y, acc[2].y);
            acc[2].z = fmaf(a, w2.z, acc[2].z); acc[2].w = fmaf(a, w2.w, acc[2].w);
            acc[3].x = fmaf(a, w3.x, acc[3].x); acc[3].y = fmaf(a, w3.y, acc[3].y);
            acc[3].z = fmaf(a, w3.z, acc[3].z); acc[3].w = fmaf(a, w3.w, acc[3].w);
        }
    }

    const float4* ad = (const float4*)(a_dst + head * NFEAT + f0);
    float4 a0 = ad[0], a1 = ad[1], a2 = ad[2], a3 = ad[3];
    float s = acc[0].x * a0.x + acc[0].y * a0.y + acc[0].z * a0.z + acc[0].w * a0.w
            + acc[1].x * a1.x + acc[1].y * a1.y + acc[1].z * a1.z + acc[1].w * a1.w
            + acc[2].x * a2.x + acc[2].y * a2.y + acc[2].z * a2.z + acc[2].w * a2.w
            + acc[3].x * a3.x + acc[3].y * a3.y + acc[3].z * a3.z + acc[3].w * a3.w;
    s += __shfl_xor_sync(0xffffffffu, s, 1);
    s += __shfl_xor_sync(0xffffffffu, s, 2);
    float e = expf(s);

    float vals[16];
#pragma unroll
    for (int i = 0; i < 4; i++) ((float4*)vals)[i] = acc[i];

    int bh = bb * NHEADS + head;
    size_t base = ((size_t)bh * NNODE + (n0 + node)) * NFEAT + f0;
    __nv_bfloat16 hi16[16], lo16[16];
#pragma unroll
    for (int i = 0; i < 16; i++) {
        float g = vals[i] * e;
        __nv_bfloat16 hi = __float2bfloat16(g);
        hi16[i] = hi;
        lo16[i] = __float2bfloat16(g - __bfloat162float(hi));
    }
#pragma unroll
    for (int i = 0; i < 2; i++) {
        ((uint4*)(d_gh + base))[i] = ((const uint4*)hi16)[i];
        ((uint4*)(d_gl + base))[i] = ((const uint4*)lo16)[i];
    }
    if ((t & 3) == 0) {
        __nv_bfloat16 ehi = __float2bfloat16(e);
        d_e[bh * NNODE + n0 + node]  = e;
        d_eh[bh * NNODE + n0 + node] = ehi;
        d_el[bh * NNODE + n0 + node] = __float2bfloat16(e - __bfloat162float(ehi));
    }
}

// ---------------------------------------------------------------------------
// k2: num = Adj @ (g_hi + g_lo) via mma.sync, 3-stage cp.async pipeline.
//     B column 64 carries e (hi/lo) -> rowsum computed by the same MMAs.
//     Epilogue: rinv = 1/rowsum (stored for k3), out = elu(num * rinv).
// CTA 256 thr = 8 warps (4m x 2n). Tile M=128, N=64(+e), one bh.
// ---------------------------------------------------------------------------
#define APAD 72                              // bf16 per smem row (144 B)
#define A_BYTES (128 * APAD * 2)             // 18432
#define BP_BYTES (64 * APAD * 2)             // 9216 per panel
#define STAGE_BYTES (A_BYTES + 2 * BP_BYTES) // 36864
#define NSTAGE 3
#define K2_SMEM (NSTAGE * STAGE_BYTES)       // 110592

__device__ __forceinline__ void k2_load(char* smem, int stage, int c, int tid,
        const __nv_bfloat16* srcA, const __nv_bfloat16* srcH, const __nv_bfloat16* srcL,
        const __nv_bfloat16* eh, const __nv_bfloat16* el) {
    char* sbase = smem + stage * STAGE_BYTES;
    const int cb = c * 64;
    uint32_t aB = smem_u32(sbase);
#pragma unroll
    for (int i = 0; i < 4; i++) {
        int ch = tid + i * 256;
        int rr = ch >> 3, cc = ch & 7;
        CP_ASYNC16(aB + rr * 144 + cc * 16, srcA + (size_t)rr * NNODE + cb + cc * 8);
    }
    uint32_t bB = aB + A_BYTES;
#pragma unroll
    for (int i = 0; i < 4; i++) {
        int ch = tid + i * 256;
        int p = ch >> 9, r = (ch >> 3) & 63, cc = ch & 7;
        const __nv_bfloat16* src = p ? srcL : srcH;
        CP_ASYNC16(bB + p * BP_BYTES + r * 144 + cc * 16, src + (size_t)(cb + r) * NFEAT + cc * 8);
    }
    if (tid < 128) {       // e column (col 64) + zero cols 65-71
        int p = tid >> 6, r = tid & 63;
        __nv_bfloat16 ev = p ? el[cb + r] : eh[cb + r];
        uint4 v; v.x = (uint32_t)__bfloat16_as_ushort(ev); v.y = v.z = v.w = 0;
        *(uint4*)(sbase + A_BYTES + p * BP_BYTES + r * 144 + 128) = v;
    }
}

__global__ void __launch_bounds__(256, 2) k2_mma(float* __restrict__ out_main) {
    extern __shared__ char smem[];
    const int tid = threadIdx.x;
    const int warp = tid >> 5, lane = tid & 31;
    const int wm = warp & 3, wn = warp >> 2;
    const int m0 = blockIdx.x * 128;
    const int bh = blockIdx.y;

    const __nv_bfloat16* srcA = d_adjh + (size_t)m0 * NNODE;
    const __nv_bfloat16* srcH = d_gh + (size_t)bh * NNODE * NFEAT;
    const __nv_bfloat16* srcL = d_gl + (size_t)bh * NNODE * NFEAT;
    const __nv_bfloat16* eh = d_eh + bh * NNODE;
    const __nv_bfloat16* el = d_el + bh * NNODE;

    float acc[2][5][4];
#pragma unroll
    for (int mt = 0; mt < 2; mt++)
#pragma unroll
        for (int nt = 0; nt < 5; nt++)
#pragma unroll
            for (int i = 0; i < 4; i++) acc[mt][nt][i] = 0.f;

    k2_load(smem, 0, 0, tid, srcA, srcH, srcL, eh, el); CP_COMMIT();
    k2_load(smem, 1, 1, tid, srcA, srcH, srcL, eh, el); CP_COMMIT();

    for (int c = 0; c < 32; c++) {
        CP_WAIT1();
        __syncthreads();
        if (c + 2 < 32)
            k2_load(smem, (c + 2) % NSTAGE, c + 2, tid, srcA, srcH, srcL, eh, el);
        CP_COMMIT();

        const __nv_bfloat16* sA = (const __nv_bfloat16*)(smem + (c % NSTAGE) * STAGE_BYTES);
        const __nv_bfloat16* sBh = sA + 128 * APAD;
        const __nv_bfloat16* sBl = sBh + 64 * APAD;
#pragma unroll
        for (int ks = 0; ks < 4; ks++) {
            uint32_t af[2][4];
#pragma unroll
            for (int mt = 0; mt < 2; mt++)
                ldsm_x4(af[mt], smem_u32(sA + (wm * 32 + mt * 16 + (lane & 15)) * APAD
                                            + ks * 16 + (lane >> 4) * 8));
#pragma unroll
            for (int p = 0; p < 2; p++) {
                const __nv_bfloat16* sBp = p ? sBl : sBh;
                uint32_t bfm[2][4];
#pragma unroll
                for (int np = 0; np < 2; np++)
                    ldsm_x4_t(bfm[np], smem_u32(sBp + (ks * 16 + (lane & 15)) * APAD
                                                    + wn * 32 + np * 16 + (lane >> 4) * 8));
                uint32_t bx2[2];
                if (wn == 1)
                    ldsm_x2_t(bx2, smem_u32(sBp + (ks * 16 + (lane & 15)) * APAD + 64));
#pragma unroll
                for (int mt = 0; mt < 2; mt++) {
#pragma unroll
                    for (int nt = 0; nt < 4; nt++)
                        mma_bf16(acc[mt][nt], af[mt], bfm[nt >> 1] + (nt & 1) * 2);
                }
                if (wn == 1) {
#pragma unroll
                    for (int mt = 0; mt < 2; mt++)
                        mma_bf16(acc[mt][4], af[mt], bx2);
                }
            }
        }
    }

    // ---- epilogue: rinv via smem exchange, elu(num*rinv) stores ----
    float* srinv = (float*)smem;             // 128 floats, overlays stage 0
    if (wn == 1 && (lane & 3) == 0) {
#pragma unroll
        for (int mt = 0; mt < 2; mt++) {
            int rl = wm * 32 + mt * 16 + (lane >> 2);
            float v0 = 1.f / acc[mt][4][0];
            float v1 = 1.f / acc[mt][4][2];
            srinv[rl] = v0;  srinv[rl + 8] = v1;
            d_rinv[bh * NNODE + m0 + rl] = v0;
            d_rinv[bh * NNODE + m0 + rl + 8] = v1;
        }
    }
    __syncthreads();

    if (out_main) {
        const int b = bh >> 2, head = bh & 3;
#pragma unroll
        for (int mt = 0; mt < 2; mt++) {
            int rl = wm * 32 + mt * 16 + (lane >> 2);
            float ri0 = srinv[rl];
            float ri1 = srinv[rl + 8];
            float* o0 = out_main + ((size_t)b * NNODE + m0 + rl) * (NHEADS * NFEAT) + head * NFEAT;
            float* o1 = o0 + 8 * (NHEADS * NFEAT);
#pragma unroll
            for (int nt = 0; nt < 4; nt++) {
                int col = wn * 32 + nt * 8 + (lane & 3) * 2;
                float x0 = acc[mt][nt][0] * ri0, x1 = acc[mt][nt][1] * ri0;
                float x2 = acc[mt][nt][2] * ri1, x3 = acc[mt][nt][3] * ri1;
                x0 = x0 > 0.f ? x0 : expm1f(x0);
                x1 = x1 > 0.f ? x1 : expm1f(x1);
                x2 = x2 > 0.f ? x2 : expm1f(x2);
                x3 = x3 > 0.f ? x3 : expm1f(x3);
                *(float2*)(o0 + col) = make_float2(x0, x1);
                *(float2*)(o1 + col) = make_float2(x2, x3);
            }
        }
    }
}

// ---------------------------------------------------------------------------
// k3: att[bh][i][j] = bit ? e_j * rinv_i : 0  (streaming float4 stores)
// ---------------------------------------------------------------------------
__global__ void k3_att(float* __restrict__ att) {
    __shared__ float s_e[NNODE];
    int bh = blockIdx.y;
    for (int i = threadIdx.x; i < NNODE; i += 256)
        s_e[i] = d_e[bh * NNODE + i];
    __syncthreads();

    int warp = threadIdx.x >> 5, lane = threadIdx.x & 31;
    int row = blockIdx.x * 8 + warp;
    float rinv = d_rinv[bh * NNODE + row];
    const unsigned* bw = d_bits + row * 64;
    float* dst = att + ((size_t)bh * NNODE + row) * NNODE;

#pragma unroll
    for (int c = 0; c < 16; c++) {
        int j = c * 128 + lane * 4;
        unsigned m = bw[j >> 5] >> (j & 31);
        float4 v;
        v.x = (m & 1u) ? s_e[j]     * rinv : 0.f;
        v.y = (m & 2u) ? s_e[j + 1] * rinv : 0.f;
        v.z = (m & 4u) ? s_e[j + 2] * rinv : 0.f;
        v.w = (m & 8u) ? s_e[j + 3] * rinv : 0.f;
        __stcs((float4*)(dst + j), v);
    }
}

// ---------------------------------------------------------------------------
extern "C" void kernel_launch(void* const* d_in, const int* in_sizes, int n_in,
                              void* d_out, int out_size) {
    const float* inp   = (const float*)d_in[0];
    const int*   adj   = (const int*)  d_in[1];
    const float* W     = (const float*)d_in[2];
    const float* bias  = (const float*)d_in[3];
    const float* a_dst = (const float*)d_in[5];
    (void)in_sizes; (void)n_in;

    float* out = (float*)d_out;
    const size_t OUT_E = (size_t)BSZ * NNODE * NHEADS * NFEAT;
    const size_t ATT_E = (size_t)BSZ * NHEADS * NNODE * NNODE;
    float* out_main = nullptr;
    float* out_att  = nullptr;
    if ((size_t)out_size >= OUT_E + ATT_E) { out_main = out; out_att = out + OUT_E; }
    else if ((size_t)out_size == ATT_E)    { out_att = out; }
    else                                   { out_main = out; }

    static bool attr_set = false;
    if (!attr_set) {
        cudaFuncSetAttribute(k2_mma, cudaFuncAttributeMaxDynamicSharedMemorySize, K2_SMEM);
        attr_set = true;
    }

    kA_prep<<<K1_BLOCKS + (NNODE * NNODE) / 256, 256>>>(inp, adj, W, bias, a_dst);
    k2_mma<<<dim3(NNODE / 128, BH), 256, K2_SMEM>>>(out_main);
    if (out_att) k3_att<<<dim3(NNODE / 8, BH), 256>>>(out_att);
}

// round 6
// speedup vs baseline: 7.1743x; 1.1504x over previous
#include <cuda_runtime.h>
#include <cuda_bf16.h>
#include <math.h>
#include <stdint.h>

#define BSZ 4
#define NNODE 2048
#define NINP 128
#define NFEAT 64
#define NHEADS 4
#define BH (BSZ*NHEADS)

// ---- scratch (static device globals; no allocation) ----
__device__ __nv_bfloat16 d_adjh[(size_t)NNODE*NNODE];       // Adj as bf16 (8 MB)
__device__ unsigned      d_bits[NNODE*(NNODE/32)];          // packed adjacency
__device__ __nv_bfloat16 d_gh[(size_t)BH*NNODE*NFEAT];      // hi(e*h)  [bh][j][f]
__device__ __nv_bfloat16 d_gl[(size_t)BH*NNODE*NFEAT];      // lo residual
__device__ __nv_bfloat16 d_eh[BH*NNODE];                    // hi(e)
__device__ __nv_bfloat16 d_el[BH*NNODE];                    // lo(e)
__device__ float         d_e[BH*NNODE];                     // exp(s_dst) fp32
__device__ float         d_rinv[BH*NNODE];                  // 1/(Adj@e)

__device__ __forceinline__ uint32_t smem_u32(const void* p) {
    return (uint32_t)__cvta_generic_to_shared(p);
}
__device__ __forceinline__ void ldsm_x4(uint32_t* r, uint32_t addr) {
    asm volatile("ldmatrix.sync.aligned.m8n8.x4.shared.b16 {%0,%1,%2,%3}, [%4];"
                 : "=r"(r[0]), "=r"(r[1]), "=r"(r[2]), "=r"(r[3]) : "r"(addr));
}
__device__ __forceinline__ void ldsm_x4_t(uint32_t* r, uint32_t addr) {
    asm volatile("ldmatrix.sync.aligned.m8n8.x4.trans.shared.b16 {%0,%1,%2,%3}, [%4];"
                 : "=r"(r[0]), "=r"(r[1]), "=r"(r[2]), "=r"(r[3]) : "r"(addr));
}
__device__ __forceinline__ void ldsm_x2_t(uint32_t* r, uint32_t addr) {
    asm volatile("ldmatrix.sync.aligned.m8n8.x2.trans.shared.b16 {%0,%1}, [%2];"
                 : "=r"(r[0]), "=r"(r[1]) : "r"(addr));
}
__device__ __forceinline__ void mma_bf16(float* c, const uint32_t* a, const uint32_t* b) {
    asm volatile(
        "mma.sync.aligned.m16n8k16.row.col.f32.bf16.bf16.f32 "
        "{%0,%1,%2,%3}, {%4,%5,%6,%7}, {%8,%9}, {%0,%1,%2,%3};"
        : "+f"(c[0]), "+f"(c[1]), "+f"(c[2]), "+f"(c[3])
        : "r"(a[0]), "r"(a[1]), "r"(a[2]), "r"(a[3]), "r"(b[0]), "r"(b[1]));
}
#define CP_ASYNC16(dst, src) \
    asm volatile("cp.async.cg.shared.global [%0], [%1], 16;" :: "r"(dst), "l"(src))
#define CP_COMMIT() asm volatile("cp.async.commit_group;")
#define CP_WAIT1()  asm volatile("cp.async.wait_group 1;")

// ---------------------------------------------------------------------------
// kA: fused k0 (adj pack, vectorized) + k1 (register-blocked projection).
//   blocks [0, 2048): k0, one adj row each
//   blocks [2048, 2048+128): k1, 256-node tile x (head, batch)
// ---------------------------------------------------------------------------
#define K0_BLOCKS NNODE      // 2048
#define K1_BLOCKS 128

__global__ void __launch_bounds__(256) kA_prep(
        const float* __restrict__ inp, const int* __restrict__ adj,
        const float* __restrict__ W, const float* __restrict__ bias,
        const float* __restrict__ a_dst) {
    __shared__ float s_inp[256 * 20];   // [node][k] stride 20
    __shared__ float s_W[16 * 68];      // [k][f]    stride 68
    const int bid = blockIdx.x;
    const int t = threadIdx.x;

    if (bid < K0_BLOCKS) {
        // ---- k0: adj row -> bf16 row + bitmask (8 elems/thread) ----
        const int row = bid;
        const int j0 = t * 8;
        const int4* src = (const int4*)(adj + (size_t)row * NNODE + j0);
        int4 v0 = src[0], v1 = src[1];
        const unsigned short ONE = 0x3F80;
        unsigned short h[8];
        unsigned m = 0;
        h[0] = v0.x ? ONE : 0; m |= (v0.x != 0) << 0;
        h[1] = v0.y ? ONE : 0; m |= (v0.y != 0) << 1;
        h[2] = v0.z ? ONE : 0; m |= (v0.z != 0) << 2;
        h[3] = v0.w ? ONE : 0; m |= (v0.w != 0) << 3;
        h[4] = v1.x ? ONE : 0; m |= (v1.x != 0) << 4;
        h[5] = v1.y ? ONE : 0; m |= (v1.y != 0) << 5;
        h[6] = v1.z ? ONE : 0; m |= (v1.z != 0) << 6;
        h[7] = v1.w ? ONE : 0; m |= (v1.w != 0) << 7;
        *(uint4*)(d_adjh + (size_t)row * NNODE + j0) = *(const uint4*)h;
        unsigned w = m
                   | (__shfl_down_sync(0xffffffffu, m, 1) << 8)
                   | (__shfl_down_sync(0xffffffffu, m, 2) << 16)
                   | (__shfl_down_sync(0xffffffffu, m, 3) << 24);
        if (((t & 31) & 3) == 0)
            d_bits[row * 64 + (j0 >> 5)] = w;
        return;
    }

    // ---- k1: thread = (nr 0..63, fq 0..3); owns 4 node-slots x 16 feats ----
    const int bid2 = bid - K0_BLOCKS;
    const int n0   = (bid2 & 7) * 256;
    const int head = (bid2 >> 3) & 3;
    const int bb   = bid2 >> 5;
    const int nr = t >> 2;
    const int fq = t & 3;
    const int f0 = fq * 16;

    float4 acc[4][4];                    // [slot][feat-quad]
    {
        float4 b0 = *(const float4*)(bias + head * NFEAT + f0);
        float4 b1 = *(const float4*)(bias + head * NFEAT + f0 + 4);
        float4 b2 = *(const float4*)(bias + head * NFEAT + f0 + 8);
        float4 b3 = *(const float4*)(bias + head * NFEAT + f0 + 12);
#pragma unroll
        for (int s = 0; s < 4; s++) {
            acc[s][0] = b0; acc[s][1] = b1; acc[s][2] = b2; acc[s][3] = b3;
        }
    }

    for (int kc = 0; kc < 8; kc++) {
        __syncthreads();
        // s_inp: 256 nodes x 16 k  (1024 float4 = 4/thread)
#pragma unroll
        for (int i = 0; i < 4; i++) {
            int li = t + i * 256;
            int n = li >> 2, q = li & 3;
            float4 v = *(const float4*)(inp + ((size_t)bb * NNODE + n0 + n) * NINP + kc * 16 + q * 4);
            *(float4*)(s_inp + n * 20 + q * 4) = v;
        }
        // s_W: 16 k x 64 f  (256 float4 = 1/thread)
        {
            int k = t >> 4, q = t & 15;
            float4 v = *(const float4*)(W + (size_t)head * NINP * NFEAT + (size_t)(kc * 16 + k) * NFEAT + q * 4);
            *(float4*)(s_W + k * 68 + q * 4) = v;
        }
        __syncthreads();
#pragma unroll
        for (int k = 0; k < 16; k++) {
            const float4* wr = (const float4*)(s_W + k * 68 + f0);
            float4 w0 = wr[0], w1 = wr[1], w2 = wr[2], w3 = wr[3];
            float a[4];
#pragma unroll
            for (int s = 0; s < 4; s++)
                a[s] = s_inp[(nr + s * 64) * 20 + k];
#pragma unroll
            for (int s = 0; s < 4; s++) {
                acc[s][0].x = fmaf(a[s], w0.x, acc[s][0].x); acc[s][0].y = fmaf(a[s], w0.y, acc[s][0].y);
                acc[s][0].z = fmaf(a[s], w0.z, acc[s][0].z); acc[s][0].w = fmaf(a[s], w0.w, acc[s][0].w);
                acc[s][1].x = fmaf(a[s], w1.x, acc[s][1].x); acc[s][1].y = fmaf(a[s], w1.y, acc[s][1].y);
                acc[s][1].z = fmaf(a[s], w1.z, acc[s][1].z); acc[s][1].w = fmaf(a[s], w1.w, acc[s][1].w);
                acc[s][2].x = fmaf(a[s], w2.x, acc[s][2].x); acc[s][2].y = fmaf(a[s], w2.y, acc[s][2].y);
                acc[s][2].z = fmaf(a[s], w2.z, acc[s][2].z); acc[s][2].w = fmaf(a[s], w2.w, acc[s][2].w);
                acc[s][3].x = fmaf(a[s], w3.x, acc[s][3].x); acc[s][3].y = fmaf(a[s], w3.y, acc[s][3].y);
                acc[s][3].z = fmaf(a[s], w3.z, acc[s][3].z); acc[s][3].w = fmaf(a[s], w3.w, acc[s][3].w);
            }
        }
    }

    // epilogue: s_dst per slot, reduce across fq lanes (xor 1,2), exp, hi/lo stores
    float4 a0 = *(const float4*)(a_dst + head * NFEAT + f0);
    float4 a1 = *(const float4*)(a_dst + head * NFEAT + f0 + 4);
    float4 a2 = *(const float4*)(a_dst + head * NFEAT + f0 + 8);
    float4 a3 = *(const float4*)(a_dst + head * NFEAT + f0 + 12);
    const int bh = bb * NHEADS + head;
#pragma unroll
    for (int s = 0; s < 4; s++) {
        float p = acc[s][0].x * a0.x + acc[s][0].y * a0.y + acc[s][0].z * a0.z + acc[s][0].w * a0.w
                + acc[s][1].x * a1.x + acc[s][1].y * a1.y + acc[s][1].z * a1.z + acc[s][1].w * a1.w
                + acc[s][2].x * a2.x + acc[s][2].y * a2.y + acc[s][2].z * a2.z + acc[s][2].w * a2.w
                + acc[s][3].x * a3.x + acc[s][3].y * a3.y + acc[s][3].z * a3.z + acc[s][3].w * a3.w;
        p += __shfl_xor_sync(0xffffffffu, p, 1);
        p += __shfl_xor_sync(0xffffffffu, p, 2);
        float e = expf(p);

        float vals[16];
#pragma unroll
        for (int i = 0; i < 4; i++) ((float4*)vals)[i] = acc[s][i];
        __nv_bfloat16 hi16[16], lo16[16];
#pragma unroll
        for (int i = 0; i < 16; i++) {
            float g = vals[i] * e;
            __nv_bfloat16 hi = __float2bfloat16(g);
            hi16[i] = hi;
            lo16[i] = __float2bfloat16(g - __bfloat162float(hi));
        }
        const int node = n0 + nr + s * 64;
        size_t base = ((size_t)bh * NNODE + node) * NFEAT + f0;
#pragma unroll
        for (int i = 0; i < 2; i++) {
            ((uint4*)(d_gh + base))[i] = ((const uint4*)hi16)[i];
            ((uint4*)(d_gl + base))[i] = ((const uint4*)lo16)[i];
        }
        if (fq == 0) {
            __nv_bfloat16 ehi = __float2bfloat16(e);
            d_e[bh * NNODE + node]  = e;
            d_eh[bh * NNODE + node] = ehi;
            d_el[bh * NNODE + node] = __float2bfloat16(e - __bfloat162float(ehi));
        }
    }
}

// ---------------------------------------------------------------------------
// k2: num = Adj @ (g_hi + g_lo) via mma.sync, 3-stage cp.async pipeline.
//     B column 64 carries e (hi/lo) -> rowsum from the same MMAs.
//     Epilogue: rinv = 1/rowsum (stored for k3), out = elu(num * rinv).
// ---------------------------------------------------------------------------
#define APAD 72                              // bf16 per smem row (144 B)
#define A_BYTES (128 * APAD * 2)             // 18432
#define BP_BYTES (64 * APAD * 2)             // 9216 per panel
#define STAGE_BYTES (A_BYTES + 2 * BP_BYTES) // 36864
#define NSTAGE 3
#define K2_SMEM (NSTAGE * STAGE_BYTES)       // 110592

__device__ __forceinline__ void k2_load(char* smem, int stage, int c, int tid,
        const __nv_bfloat16* srcA, const __nv_bfloat16* srcH, const __nv_bfloat16* srcL,
        const __nv_bfloat16* eh, const __nv_bfloat16* el) {
    char* sbase = smem + stage * STAGE_BYTES;
    const int cb = c * 64;
    uint32_t aB = smem_u32(sbase);
#pragma unroll
    for (int i = 0; i < 4; i++) {
        int ch = tid + i * 256;
        int rr = ch >> 3, cc = ch & 7;
        CP_ASYNC16(aB + rr * 144 + cc * 16, srcA + (size_t)rr * NNODE + cb + cc * 8);
    }
    uint32_t bB = aB + A_BYTES;
#pragma unroll
    for (int i = 0; i < 4; i++) {
        int ch = tid + i * 256;
        int p = ch >> 9, r = (ch >> 3) & 63, cc = ch & 7;
        const __nv_bfloat16* src = p ? srcL : srcH;
        CP_ASYNC16(bB + p * BP_BYTES + r * 144 + cc * 16, src + (size_t)(cb + r) * NFEAT + cc * 8);
    }
    if (tid < 128) {       // e column (col 64) + zero cols 65-71
        int p = tid >> 6, r = tid & 63;
        __nv_bfloat16 ev = p ? el[cb + r] : eh[cb + r];
        uint4 v; v.x = (uint32_t)__bfloat16_as_ushort(ev); v.y = v.z = v.w = 0;
        *(uint4*)(sbase + A_BYTES + p * BP_BYTES + r * 144 + 128) = v;
    }
}

__global__ void __launch_bounds__(256, 2) k2_mma(float* __restrict__ out_main) {
    extern __shared__ char smem[];
    const int tid = threadIdx.x;
    const int warp = tid >> 5, lane = tid & 31;
    const int wm = warp & 3, wn = warp >> 2;
    const int m0 = blockIdx.x * 128;
    const int bh = blockIdx.y;

    const __nv_bfloat16* srcA = d_adjh + (size_t)m0 * NNODE;
    const __nv_bfloat16* srcH = d_gh + (size_t)bh * NNODE * NFEAT;
    const __nv_bfloat16* srcL = d_gl + (size_t)bh * NNODE * NFEAT;
    const __nv_bfloat16* eh = d_eh + bh * NNODE;
    const __nv_bfloat16* el = d_el + bh * NNODE;

    float acc[2][5][4];
#pragma unroll
    for (int mt = 0; mt < 2; mt++)
#pragma unroll
        for (int nt = 0; nt < 5; nt++)
#pragma unroll
            for (int i = 0; i < 4; i++) acc[mt][nt][i] = 0.f;

    k2_load(smem, 0, 0, tid, srcA, srcH, srcL, eh, el); CP_COMMIT();
    k2_load(smem, 1, 1, tid, srcA, srcH, srcL, eh, el); CP_COMMIT();

    for (int c = 0; c < 32; c++) {
        CP_WAIT1();
        __syncthreads();
        if (c + 2 < 32)
            k2_load(smem, (c + 2) % NSTAGE, c + 2, tid, srcA, srcH, srcL, eh, el);
        CP_COMMIT();

        const __nv_bfloat16* sA = (const __nv_bfloat16*)(smem + (c % NSTAGE) * STAGE_BYTES);
        const __nv_bfloat16* sBh = sA + 128 * APAD;
        const __nv_bfloat16* sBl = sBh + 64 * APAD;
#pragma unroll
        for (int ks = 0; ks < 4; ks++) {
            uint32_t af[2][4];
#pragma unroll
            for (int mt = 0; mt < 2; mt++)
                ldsm_x4(af[mt], smem_u32(sA + (wm * 32 + mt * 16 + (lane & 15)) * APAD
                                            + ks * 16 + (lane >> 4) * 8));
#pragma unroll
            for (int p = 0; p < 2; p++) {
                const __nv_bfloat16* sBp = p ? sBl : sBh;
                uint32_t bfm[2][4];
#pragma unroll
                for (int np = 0; np < 2; np++)
                    ldsm_x4_t(bfm[np], smem_u32(sBp + (ks * 16 + (lane & 15)) * APAD
                                                    + wn * 32 + np * 16 + (lane >> 4) * 8));
                uint32_t bx2[2];
                if (wn == 1)
                    ldsm_x2_t(bx2, smem_u32(sBp + (ks * 16 + (lane & 15)) * APAD + 64));
#pragma unroll
                for (int mt = 0; mt < 2; mt++) {
#pragma unroll
                    for (int nt = 0; nt < 4; nt++)
                        mma_bf16(acc[mt][nt], af[mt], bfm[nt >> 1] + (nt & 1) * 2);
                }
                if (wn == 1) {
#pragma unroll
                    for (int mt = 0; mt < 2; mt++)
                        mma_bf16(acc[mt][4], af[mt], bx2);
                }
            }
        }
    }

    // ---- epilogue: rinv via smem exchange, elu(num*rinv) stores ----
    float* srinv = (float*)smem;
    if (wn == 1 && (lane & 3) == 0) {
#pragma unroll
        for (int mt = 0; mt < 2; mt++) {
            int rl = wm * 32 + mt * 16 + (lane >> 2);
            float v0 = 1.f / acc[mt][4][0];
            float v1 = 1.f / acc[mt][4][2];
            srinv[rl] = v0;  srinv[rl + 8] = v1;
            d_rinv[bh * NNODE + m0 + rl] = v0;
            d_rinv[bh * NNODE + m0 + rl + 8] = v1;
        }
    }
    __syncthreads();

    if (out_main) {
        const int b = bh >> 2, head = bh & 3;
#pragma unroll
        for (int mt = 0; mt < 2; mt++) {
            int rl = wm * 32 + mt * 16 + (lane >> 2);
            float ri0 = srinv[rl];
            float ri1 = srinv[rl + 8];
            float* o0 = out_main + ((size_t)b * NNODE + m0 + rl) * (NHEADS * NFEAT) + head * NFEAT;
            float* o1 = o0 + 8 * (NHEADS * NFEAT);
#pragma unroll
            for (int nt = 0; nt < 4; nt++) {
                int col = wn * 32 + nt * 8 + (lane & 3) * 2;
                float x0 = acc[mt][nt][0] * ri0, x1 = acc[mt][nt][1] * ri0;
                float x2 = acc[mt][nt][2] * ri1, x3 = acc[mt][nt][3] * ri1;
                x0 = x0 > 0.f ? x0 : expm1f(x0);
                x1 = x1 > 0.f ? x1 : expm1f(x1);
                x2 = x2 > 0.f ? x2 : expm1f(x2);
                x3 = x3 > 0.f ? x3 : expm1f(x3);
                *(float2*)(o0 + col) = make_float2(x0, x1);
                *(float2*)(o1 + col) = make_float2(x2, x3);
            }
        }
    }
}

// ---------------------------------------------------------------------------
// k3: att[bh][i][j] = bit ? e_j * rinv_i : 0  (streaming float4 stores)
// ---------------------------------------------------------------------------
__global__ void k3_att(float* __restrict__ att) {
    __shared__ float s_e[NNODE];
    int bh = blockIdx.y;
    for (int i = threadIdx.x; i < NNODE; i += 256)
        s_e[i] = d_e[bh * NNODE + i];
    __syncthreads();

    int warp = threadIdx.x >> 5, lane = threadIdx.x & 31;
    int row = blockIdx.x * 8 + warp;
    float rinv = d_rinv[bh * NNODE + row];
    const unsigned* bw = d_bits + row * 64;
    float* dst = att + ((size_t)bh * NNODE + row) * NNODE;

#pragma unroll
    for (int c = 0; c < 16; c++) {
        int j = c * 128 + lane * 4;
        unsigned m = bw[j >> 5] >> (j & 31);
        float4 v;
        v.x = (m & 1u) ? s_e[j]     * rinv : 0.f;
        v.y = (m & 2u) ? s_e[j + 1] * rinv : 0.f;
        v.z = (m & 4u) ? s_e[j + 2] * rinv : 0.f;
        v.w = (m & 8u) ? s_e[j + 3] * rinv : 0.f;
        __stcs((float4*)(dst + j), v);
    }
}

// ---------------------------------------------------------------------------
extern "C" void kernel_launch(void* const* d_in, const int* in_sizes, int n_in,
                              void* d_out, int out_size) {
    const float* inp   = (const float*)d_in[0];
    const int*   adj   = (const int*)  d_in[1];
    const float* W     = (const float*)d_in[2];
    const float* bias  = (const float*)d_in[3];
    const float* a_dst = (const float*)d_in[5];
    (void)in_sizes; (void)n_in;

    float* out = (float*)d_out;
    const size_t OUT_E = (size_t)BSZ * NNODE * NHEADS * NFEAT;
    const size_t ATT_E = (size_t)BSZ * NHEADS * NNODE * NNODE;
    float* out_main = nullptr;
    float* out_att  = nullptr;
    if ((size_t)out_size >= OUT_E + ATT_E) { out_main = out; out_att = out + OUT_E; }
    else if ((size_t)out_size == ATT_E)    { out_att = out; }
    else                                   { out_main = out; }

    static bool attr_set = false;
    if (!attr_set) {
        cudaFuncSetAttribute(k2_mma, cudaFuncAttributeMaxDynamicSharedMemorySize, K2_SMEM);
        attr_set = true;
    }

    kA_prep<<<K0_BLOCKS + K1_BLOCKS, 256>>>(inp, adj, W, bias, a_dst);
    k2_mma<<<dim3(NNODE / 128, BH), 256, K2_SMEM>>>(out_main);
    if (out_att) k3_att<<<dim3(NNODE / 8, BH), 256>>>(out_att);
}

// round 7
// speedup vs baseline: 8.1871x; 1.1412x over previous
#include <cuda_runtime.h>
#include <cuda_bf16.h>
#include <math.h>
#include <stdint.h>

#define BSZ 4
#define NNODE 2048
#define NINP 128
#define NFEAT 64
#define NHEADS 4
#define BH (BSZ*NHEADS)

// ---- scratch (static device globals; no allocation) ----
__device__ __nv_bfloat16 d_adjh[(size_t)NNODE*NNODE];       // Adj as bf16 (8 MB)
__device__ unsigned      d_bits[NNODE*(NNODE/32)];          // packed adjacency
__device__ __nv_bfloat16 d_gh[(size_t)BH*NNODE*NFEAT];      // hi(e*h)  [bh][j][f]
__device__ __nv_bfloat16 d_gl[(size_t)BH*NNODE*NFEAT];      // lo residual
__device__ __nv_bfloat16 d_eh[BH*NNODE];                    // hi(e)
__device__ __nv_bfloat16 d_el[BH*NNODE];                    // lo(e)
__device__ float         d_e[BH*NNODE];                     // exp(s_dst) fp32
__device__ float         d_rinv[BH*NNODE];                  // 1/(Adj@e)

__device__ __forceinline__ uint32_t smem_u32(const void* p) {
    return (uint32_t)__cvta_generic_to_shared(p);
}
__device__ __forceinline__ void ldsm_x4(uint32_t* r, uint32_t addr) {
    asm volatile("ldmatrix.sync.aligned.m8n8.x4.shared.b16 {%0,%1,%2,%3}, [%4];"
                 : "=r"(r[0]), "=r"(r[1]), "=r"(r[2]), "=r"(r[3]) : "r"(addr));
}
__device__ __forceinline__ void ldsm_x4_t(uint32_t* r, uint32_t addr) {
    asm volatile("ldmatrix.sync.aligned.m8n8.x4.trans.shared.b16 {%0,%1,%2,%3}, [%4];"
                 : "=r"(r[0]), "=r"(r[1]), "=r"(r[2]), "=r"(r[3]) : "r"(addr));
}
__device__ __forceinline__ void ldsm_x2_t(uint32_t* r, uint32_t addr) {
    asm volatile("ldmatrix.sync.aligned.m8n8.x2.trans.shared.b16 {%0,%1}, [%2];"
                 : "=r"(r[0]), "=r"(r[1]) : "r"(addr));
}
__device__ __forceinline__ void mma_bf16(float* c, const uint32_t* a, const uint32_t* b) {
    asm volatile(
        "mma.sync.aligned.m16n8k16.row.col.f32.bf16.bf16.f32 "
        "{%0,%1,%2,%3}, {%4,%5,%6,%7}, {%8,%9}, {%0,%1,%2,%3};"
        : "+f"(c[0]), "+f"(c[1]), "+f"(c[2]), "+f"(c[3])
        : "r"(a[0]), "r"(a[1]), "r"(a[2]), "r"(a[3]), "r"(b[0]), "r"(b[1]));
}
#define CP_ASYNC16(dst, src) \
    asm volatile("cp.async.cg.shared.global [%0], [%1], 16;" :: "r"(dst), "l"(src))
#define CP_COMMIT() asm volatile("cp.async.commit_group;")
#define CP_WAIT1()  asm volatile("cp.async.wait_group 1;")

// ---------------------------------------------------------------------------
// k0: adj int32 -> bf16 + bitmask. Lean: no smem, minimal regs, full occupancy.
// ---------------------------------------------------------------------------
__global__ void __launch_bounds__(256) k0_pack(const int* __restrict__ adj) {
    const int row = blockIdx.x;
    const int t = threadIdx.x;
    const int j0 = t * 8;
    const int4* src = (const int4*)(adj + (size_t)row * NNODE + j0);
    int4 v0 = src[0], v1 = src[1];
    const unsigned short ONE = 0x3F80;
    unsigned short h[8];
    unsigned m = 0;
    h[0] = v0.x ? ONE : 0; m |= (v0.x != 0) << 0;
    h[1] = v0.y ? ONE : 0; m |= (v0.y != 0) << 1;
    h[2] = v0.z ? ONE : 0; m |= (v0.z != 0) << 2;
    h[3] = v0.w ? ONE : 0; m |= (v0.w != 0) << 3;
    h[4] = v1.x ? ONE : 0; m |= (v1.x != 0) << 4;
    h[5] = v1.y ? ONE : 0; m |= (v1.y != 0) << 5;
    h[6] = v1.z ? ONE : 0; m |= (v1.z != 0) << 6;
    h[7] = v1.w ? ONE : 0; m |= (v1.w != 0) << 7;
    *(uint4*)(d_adjh + (size_t)row * NNODE + j0) = *(const uint4*)h;
    unsigned w = m
               | (__shfl_down_sync(0xffffffffu, m, 1) << 8)
               | (__shfl_down_sync(0xffffffffu, m, 2) << 16)
               | (__shfl_down_sync(0xffffffffu, m, 3) << 24);
    if (((t & 31) & 3) == 0)
        d_bits[row * 64 + (j0 >> 5)] = w;
}

// ---------------------------------------------------------------------------
// k1: register-blocked projection. thread = (nr 0..63, fq 0..3);
//     owns 4 node-slots x 16 feats. 128 CTAs = one wave.
// ---------------------------------------------------------------------------
__global__ void __launch_bounds__(256) k1_proj(
        const float* __restrict__ inp, const float* __restrict__ W,
        const float* __restrict__ bias, const float* __restrict__ a_dst) {
    __shared__ float s_inp[256 * 20];   // [node][k] stride 20
    __shared__ float s_W[16 * 68];      // [k][f]    stride 68
    const int bid2 = blockIdx.x;
    const int t = threadIdx.x;
    const int n0   = (bid2 & 7) * 256;
    const int head = (bid2 >> 3) & 3;
    const int bb   = bid2 >> 5;
    const int nr = t >> 2;
    const int fq = t & 3;
    const int f0 = fq * 16;

    float4 acc[4][4];                    // [slot][feat-quad]
    {
        float4 b0 = *(const float4*)(bias + head * NFEAT + f0);
        float4 b1 = *(const float4*)(bias + head * NFEAT + f0 + 4);
        float4 b2 = *(const float4*)(bias + head * NFEAT + f0 + 8);
        float4 b3 = *(const float4*)(bias + head * NFEAT + f0 + 12);
#pragma unroll
        for (int s = 0; s < 4; s++) {
            acc[s][0] = b0; acc[s][1] = b1; acc[s][2] = b2; acc[s][3] = b3;
        }
    }

    for (int kc = 0; kc < 8; kc++) {
        __syncthreads();
#pragma unroll
        for (int i = 0; i < 4; i++) {
            int li = t + i * 256;
            int n = li >> 2, q = li & 3;
            float4 v = *(const float4*)(inp + ((size_t)bb * NNODE + n0 + n) * NINP + kc * 16 + q * 4);
            *(float4*)(s_inp + n * 20 + q * 4) = v;
        }
        {
            int k = t >> 4, q = t & 15;
            float4 v = *(const float4*)(W + (size_t)head * NINP * NFEAT + (size_t)(kc * 16 + k) * NFEAT + q * 4);
            *(float4*)(s_W + k * 68 + q * 4) = v;
        }
        __syncthreads();
#pragma unroll
        for (int k = 0; k < 16; k++) {
            const float4* wr = (const float4*)(s_W + k * 68 + f0);
            float4 w0 = wr[0], w1 = wr[1], w2 = wr[2], w3 = wr[3];
            float a[4];
#pragma unroll
            for (int s = 0; s < 4; s++)
                a[s] = s_inp[(nr + s * 64) * 20 + k];
#pragma unroll
            for (int s = 0; s < 4; s++) {
                acc[s][0].x = fmaf(a[s], w0.x, acc[s][0].x); acc[s][0].y = fmaf(a[s], w0.y, acc[s][0].y);
                acc[s][0].z = fmaf(a[s], w0.z, acc[s][0].z); acc[s][0].w = fmaf(a[s], w0.w, acc[s][0].w);
                acc[s][1].x = fmaf(a[s], w1.x, acc[s][1].x); acc[s][1].y = fmaf(a[s], w1.y, acc[s][1].y);
                acc[s][1].z = fmaf(a[s], w1.z, acc[s][1].z); acc[s][1].w = fmaf(a[s], w1.w, acc[s][1].w);
                acc[s][2].x = fmaf(a[s], w2.x, acc[s][2].x); acc[s][2].y = fmaf(a[s], w2.y, acc[s][2].y);
                acc[s][2].z = fmaf(a[s], w2.z, acc[s][2].z); acc[s][2].w = fmaf(a[s], w2.w, acc[s][2].w);
                acc[s][3].x = fmaf(a[s], w3.x, acc[s][3].x); acc[s][3].y = fmaf(a[s], w3.y, acc[s][3].y);
                acc[s][3].z = fmaf(a[s], w3.z, acc[s][3].z); acc[s][3].w = fmaf(a[s], w3.w, acc[s][3].w);
            }
        }
    }

    float4 a0 = *(const float4*)(a_dst + head * NFEAT + f0);
    float4 a1 = *(const float4*)(a_dst + head * NFEAT + f0 + 4);
    float4 a2 = *(const float4*)(a_dst + head * NFEAT + f0 + 8);
    float4 a3 = *(const float4*)(a_dst + head * NFEAT + f0 + 12);
    const int bh = bb * NHEADS + head;
#pragma unroll
    for (int s = 0; s < 4; s++) {
        float p = acc[s][0].x * a0.x + acc[s][0].y * a0.y + acc[s][0].z * a0.z + acc[s][0].w * a0.w
                + acc[s][1].x * a1.x + acc[s][1].y * a1.y + acc[s][1].z * a1.z + acc[s][1].w * a1.w
                + acc[s][2].x * a2.x + acc[s][2].y * a2.y + acc[s][2].z * a2.z + acc[s][2].w * a2.w
                + acc[s][3].x * a3.x + acc[s][3].y * a3.y + acc[s][3].z * a3.z + acc[s][3].w * a3.w;
        p += __shfl_xor_sync(0xffffffffu, p, 1);
        p += __shfl_xor_sync(0xffffffffu, p, 2);
        float e = expf(p);

        float vals[16];
#pragma unroll
        for (int i = 0; i < 4; i++) ((float4*)vals)[i] = acc[s][i];
        __nv_bfloat16 hi16[16], lo16[16];
#pragma unroll
        for (int i = 0; i < 16; i++) {
            float g = vals[i] * e;
            __nv_bfloat16 hi = __float2bfloat16(g);
            hi16[i] = hi;
            lo16[i] = __float2bfloat16(g - __bfloat162float(hi));
        }
        const int node = n0 + nr + s * 64;
        size_t base = ((size_t)bh * NNODE + node) * NFEAT + f0;
#pragma unroll
        for (int i = 0; i < 2; i++) {
            ((uint4*)(d_gh + base))[i] = ((const uint4*)hi16)[i];
            ((uint4*)(d_gl + base))[i] = ((const uint4*)lo16)[i];
        }
        if (fq == 0) {
            __nv_bfloat16 ehi = __float2bfloat16(e);
            d_e[bh * NNODE + node]  = e;
            d_eh[bh * NNODE + node] = ehi;
            d_el[bh * NNODE + node] = __float2bfloat16(e - __bfloat162float(ehi));
        }
    }
}

// ---------------------------------------------------------------------------
// k2: num = Adj @ (g_hi + g_lo) via mma.sync, 3-stage cp.async pipeline.
//     B column 64 carries e (hi/lo) -> rowsum from the same MMAs.
//     Epilogue: rinv = 1/rowsum (stored for k3), out = elu(num * rinv).
// ---------------------------------------------------------------------------
#define APAD 72                              // bf16 per smem row (144 B)
#define A_BYTES (128 * APAD * 2)             // 18432
#define BP_BYTES (64 * APAD * 2)             // 9216 per panel
#define STAGE_BYTES (A_BYTES + 2 * BP_BYTES) // 36864
#define NSTAGE 3
#define K2_SMEM (NSTAGE * STAGE_BYTES)       // 110592

__device__ __forceinline__ void k2_load(char* smem, int stage, int c, int tid,
        const __nv_bfloat16* srcA, const __nv_bfloat16* srcH, const __nv_bfloat16* srcL,
        const __nv_bfloat16* eh, const __nv_bfloat16* el) {
    char* sbase = smem + stage * STAGE_BYTES;
    const int cb = c * 64;
    uint32_t aB = smem_u32(sbase);
#pragma unroll
    for (int i = 0; i < 4; i++) {
        int ch = tid + i * 256;
        int rr = ch >> 3, cc = ch & 7;
        CP_ASYNC16(aB + rr * 144 + cc * 16, srcA + (size_t)rr * NNODE + cb + cc * 8);
    }
    uint32_t bB = aB + A_BYTES;
#pragma unroll
    for (int i = 0; i < 4; i++) {
        int ch = tid + i * 256;
        int p = ch >> 9, r = (ch >> 3) & 63, cc = ch & 7;
        const __nv_bfloat16* src = p ? srcL : srcH;
        CP_ASYNC16(bB + p * BP_BYTES + r * 144 + cc * 16, src + (size_t)(cb + r) * NFEAT + cc * 8);
    }
    if (tid < 128) {       // e column (col 64) + zero cols 65-71
        int p = tid >> 6, r = tid & 63;
        __nv_bfloat16 ev = p ? el[cb + r] : eh[cb + r];
        uint4 v; v.x = (uint32_t)__bfloat16_as_ushort(ev); v.y = v.z = v.w = 0;
        *(uint4*)(sbase + A_BYTES + p * BP_BYTES + r * 144 + 128) = v;
    }
}

__global__ void __launch_bounds__(256, 2) k2_mma(float* __restrict__ out_main) {
    extern __shared__ char smem[];
    const int tid = threadIdx.x;
    const int warp = tid >> 5, lane = tid & 31;
    const int wm = warp & 3, wn = warp >> 2;
    const int m0 = blockIdx.x * 128;
    const int bh = blockIdx.y;

    const __nv_bfloat16* srcA = d_adjh + (size_t)m0 * NNODE;
    const __nv_bfloat16* srcH = d_gh + (size_t)bh * NNODE * NFEAT;
    const __nv_bfloat16* srcL = d_gl + (size_t)bh * NNODE * NFEAT;
    const __nv_bfloat16* eh = d_eh + bh * NNODE;
    const __nv_bfloat16* el = d_el + bh * NNODE;

    float acc[2][5][4];
#pragma unroll
    for (int mt = 0; mt < 2; mt++)
#pragma unroll
        for (int nt = 0; nt < 5; nt++)
#pragma unroll
            for (int i = 0; i < 4; i++) acc[mt][nt][i] = 0.f;

    k2_load(smem, 0, 0, tid, srcA, srcH, srcL, eh, el); CP_COMMIT();
    k2_load(smem, 1, 1, tid, srcA, srcH, srcL, eh, el); CP_COMMIT();

    for (int c = 0; c < 32; c++) {
        CP_WAIT1();
        __syncthreads();
        if (c + 2 < 32)
            k2_load(smem, (c + 2) % NSTAGE, c + 2, tid, srcA, srcH, srcL, eh, el);
        CP_COMMIT();

        const __nv_bfloat16* sA = (const __nv_bfloat16*)(smem + (c % NSTAGE) * STAGE_BYTES);
        const __nv_bfloat16* sBh = sA + 128 * APAD;
        const __nv_bfloat16* sBl = sBh + 64 * APAD;
#pragma unroll
        for (int ks = 0; ks < 4; ks++) {
            uint32_t af[2][4];
#pragma unroll
            for (int mt = 0; mt < 2; mt++)
                ldsm_x4(af[mt], smem_u32(sA + (wm * 32 + mt * 16 + (lane & 15)) * APAD
                                            + ks * 16 + (lane >> 4) * 8));
#pragma unroll
            for (int p = 0; p < 2; p++) {
                const __nv_bfloat16* sBp = p ? sBl : sBh;
                uint32_t bfm[2][4];
#pragma unroll
                for (int np = 0; np < 2; np++)
                    ldsm_x4_t(bfm[np], smem_u32(sBp + (ks * 16 + (lane & 15)) * APAD
                                                    + wn * 32 + np * 16 + (lane >> 4) * 8));
                uint32_t bx2[2];
                if (wn == 1)
                    ldsm_x2_t(bx2, smem_u32(sBp + (ks * 16 + (lane & 15)) * APAD + 64));
#pragma unroll
                for (int mt = 0; mt < 2; mt++) {
#pragma unroll
                    for (int nt = 0; nt < 4; nt++)
                        mma_bf16(acc[mt][nt], af[mt], bfm[nt >> 1] + (nt & 1) * 2);
                }
                if (wn == 1) {
#pragma unroll
                    for (int mt = 0; mt < 2; mt++)
                        mma_bf16(acc[mt][4], af[mt], bx2);
                }
            }
        }
    }

    // ---- epilogue: rinv via smem exchange, elu(num*rinv) stores ----
    float* srinv = (float*)smem;
    if (wn == 1 && (lane & 3) == 0) {
#pragma unroll
        for (int mt = 0; mt < 2; mt++) {
            int rl = wm * 32 + mt * 16 + (lane >> 2);
            float v0 = 1.f / acc[mt][4][0];
            float v1 = 1.f / acc[mt][4][2];
            srinv[rl] = v0;  srinv[rl + 8] = v1;
            d_rinv[bh * NNODE + m0 + rl] = v0;
            d_rinv[bh * NNODE + m0 + rl + 8] = v1;
        }
    }
    __syncthreads();

    if (out_main) {
        const int b = bh >> 2, head = bh & 3;
#pragma unroll
        for (int mt = 0; mt < 2; mt++) {
            int rl = wm * 32 + mt * 16 + (lane >> 2);
            float ri0 = srinv[rl];
            float ri1 = srinv[rl + 8];
            float* o0 = out_main + ((size_t)b * NNODE + m0 + rl) * (NHEADS * NFEAT) + head * NFEAT;
            float* o1 = o0 + 8 * (NHEADS * NFEAT);
#pragma unroll
            for (int nt = 0; nt < 4; nt++) {
                int col = wn * 32 + nt * 8 + (lane & 3) * 2;
                float x0 = acc[mt][nt][0] * ri0, x1 = acc[mt][nt][1] * ri0;
                float x2 = acc[mt][nt][2] * ri1, x3 = acc[mt][nt][3] * ri1;
                x0 = x0 > 0.f ? x0 : expm1f(x0);
                x1 = x1 > 0.f ? x1 : expm1f(x1);
                x2 = x2 > 0.f ? x2 : expm1f(x2);
                x3 = x3 > 0.f ? x3 : expm1f(x3);
                *(float2*)(o0 + col) = make_float2(x0, x1);
                *(float2*)(o1 + col) = make_float2(x2, x3);
            }
        }
    }
}

// ---------------------------------------------------------------------------
// k3: att[bh][i][j] = bit ? e_j * rinv_i : 0  (streaming float4 stores)
// ---------------------------------------------------------------------------
__global__ void k3_att(float* __restrict__ att) {
    __shared__ float s_e[NNODE];
    int bh = blockIdx.y;
    for (int i = threadIdx.x; i < NNODE; i += 256)
        s_e[i] = d_e[bh * NNODE + i];
    __syncthreads();

    int warp = threadIdx.x >> 5, lane = threadIdx.x & 31;
    int row = blockIdx.x * 8 + warp;
    float rinv = d_rinv[bh * NNODE + row];
    const unsigned* bw = d_bits + row * 64;
    float* dst = att + ((size_t)bh * NNODE + row) * NNODE;

#pragma unroll
    for (int c = 0; c < 16; c++) {
        int j = c * 128 + lane * 4;
        unsigned m = bw[j >> 5] >> (j & 31);
        float4 v;
        v.x = (m & 1u) ? s_e[j]     * rinv : 0.f;
        v.y = (m & 2u) ? s_e[j + 1] * rinv : 0.f;
        v.z = (m & 4u) ? s_e[j + 2] * rinv : 0.f;
        v.w = (m & 8u) ? s_e[j + 3] * rinv : 0.f;
        __stcs((float4*)(dst + j), v);
    }
}

// ---------------------------------------------------------------------------
extern "C" void kernel_launch(void* const* d_in, const int* in_sizes, int n_in,
                              void* d_out, int out_size) {
    const float* inp   = (const float*)d_in[0];
    const int*   adj   = (const int*)  d_in[1];
    const float* W     = (const float*)d_in[2];
    const float* bias  = (const float*)d_in[3];
    const float* a_dst = (const float*)d_in[5];
    (void)in_sizes; (void)n_in;

    float* out = (float*)d_out;
    const size_t OUT_E = (size_t)BSZ * NNODE * NHEADS * NFEAT;
    const size_t ATT_E = (size_t)BSZ * NHEADS * NNODE * NNODE;
    float* out_main = nullptr;
    float* out_att  = nullptr;
    if ((size_t)out_size >= OUT_E + ATT_E) { out_main = out; out_att = out + OUT_E; }
    else if ((size_t)out_size == ATT_E)    { out_att = out; }
    else                                   { out_main = out; }

    static bool attr_set = false;
    if (!attr_set) {
        cudaFuncSetAttribute(k2_mma, cudaFuncAttributeMaxDynamicSharedMemorySize, K2_SMEM);
        attr_set = true;
    }

    k0_pack<<<NNODE, 256>>>(adj);
    k1_proj<<<128, 256>>>(inp, W, bias, a_dst);
    k2_mma<<<dim3(NNODE / 128, BH), 256, K2_SMEM>>>(out_main);
    if (out_att) k3_att<<<dim3(NNODE / 8, BH), 256>>>(out_att);
}